// round 1
// baseline (speedup 1.0000x reference)
#include <cuda_runtime.h>
#include <cstdint>

#define Bq 4
#define Cc 512
#define Tt 2048
#define Hh 8
#define Dd 64
#define LOG2E 1.4426950408889634f

// ---------------- scratch (device globals; no allocation) ----------------
__device__ float g_q[Bq * Hh * Tt * Dd];     // (b,h,t,d), pre-scaled by 1/sqrt(D)
__device__ float g_k[Bq * Hh * Tt * Dd];
__device__ float g_v[Bq * Hh * Tt * Dd];
__device__ float g_ao[Bq * Tt * Cc];         // attention output (B,T,C)
__device__ float g_h[Bq * Tt * Cc];          // out-proj result (pre-residual/LN)
__device__ float g_bias[Bq * Tt];            // conv1d key bias

// ---------------- kernel: conv1d bias ----------------
__global__ void bias_kernel(const float* __restrict__ sqi,
                            const float* __restrict__ wconv,
                            const float* __restrict__ bconv) {
    int idx = blockIdx.x * 256 + threadIdx.x;
    if (idx >= Bq * Tt) return;
    int b = idx >> 11, t = idx & (Tt - 1);
    float lft = (t > 0)      ? sqi[b * Tt + t - 1] : 0.f;
    float mid = sqi[b * Tt + t];
    float rgt = (t < Tt - 1) ? sqi[b * Tt + t + 1] : 0.f;
    g_bias[idx] = wconv[0] * lft + wconv[1] * mid + wconv[2] * rgt + bconv[0];
}

// ---------------- kernel: QKV projection ----------------
// qkv[b,t,j] = sum_c x[b,c,t] * w_qkv[j,c];  j-tile (64) == one head of q/k/v.
// Grid: (T/128, 3C/64, B), 256 threads, thread tile 8(t) x 4(j).
__global__ void __launch_bounds__(256) qkv_kernel(const float* __restrict__ x,
                                                  const float* __restrict__ wqkv) {
    __shared__ __align__(16) float As[16 * 132];  // [k][t] (pad 132)
    __shared__ __align__(16) float Bs[16 * 68];   // [k][j] (pad 68)
    const int tid = threadIdx.x;
    const int tx = tid & 15, ty = tid >> 4;
    const int t0 = blockIdx.x * 128;
    const int j0 = blockIdx.y * 64;
    const int b = blockIdx.z;
    const float* xb = x + (size_t)b * Cc * Tt;

    float acc[8][4];
#pragma unroll
    for (int i = 0; i < 8; i++)
#pragma unroll
        for (int j = 0; j < 4; j++) acc[i][j] = 0.f;

    for (int k0 = 0; k0 < Cc; k0 += 16) {
        // As: x rows are contiguous in t -> coalesced float4, conflict-free STS
#pragma unroll
        for (int r = 0; r < 2; r++) {
            int f = tid + r * 256;          // 512 float4
            int cc = f >> 5, t4 = f & 31;
            float4 v = *(const float4*)(xb + (size_t)(k0 + cc) * Tt + t0 + t4 * 4);
            *(float4*)&As[cc * 132 + t4 * 4] = v;
        }
        // Bs: w_qkv row-major in c; transpose to [k][j]
        {
            int j = tid >> 2, c4 = tid & 3;
            float4 w = *(const float4*)(wqkv + (size_t)(j0 + j) * Cc + k0 + c4 * 4);
            Bs[(c4 * 4 + 0) * 68 + j] = w.x;
            Bs[(c4 * 4 + 1) * 68 + j] = w.y;
            Bs[(c4 * 4 + 2) * 68 + j] = w.z;
            Bs[(c4 * 4 + 3) * 68 + j] = w.w;
        }
        __syncthreads();
#pragma unroll
        for (int cc = 0; cc < 16; cc++) {
            float4 a0 = *(const float4*)&As[cc * 132 + ty * 8];
            float4 a1 = *(const float4*)&As[cc * 132 + ty * 8 + 4];
            float4 bb = *(const float4*)&Bs[cc * 68 + tx * 4];
            float av[8] = {a0.x, a0.y, a0.z, a0.w, a1.x, a1.y, a1.z, a1.w};
            float bv[4] = {bb.x, bb.y, bb.z, bb.w};
#pragma unroll
            for (int i = 0; i < 8; i++)
#pragma unroll
                for (int j = 0; j < 4; j++) acc[i][j] += av[i] * bv[j];
        }
        __syncthreads();
    }

    const int mat = j0 >> 9;                 // 0=q, 1=k, 2=v
    const int hh = (j0 & 511) >> 6;
    const float scl = (mat == 0) ? 0.125f : 1.0f;   // fold 1/sqrt(D) into Q
    float* dst = (mat == 0) ? g_q : (mat == 1) ? g_k : g_v;
    dst += (((size_t)(b * Hh + hh)) * Tt + t0) * Dd + tx * 4;
#pragma unroll
    for (int i = 0; i < 8; i++) {
        float4 o = make_float4(acc[i][0] * scl, acc[i][1] * scl,
                               acc[i][2] * scl, acc[i][3] * scl);
        *(float4*)(dst + (size_t)(ty * 8 + i) * Dd) = o;
    }
}

// ---------------- kernel: fused flash attention ----------------
// Grid: (T/128, H, B), 256 threads, q-tile 128, kv-tile 64.
// Thread tile: 8 query rows (ty) x 4 key cols / 4 d cols (tx).
#define ATTN_SMEM_FLOATS (64 * 132 + 64 * 68 + 64 * 68 + 128 * 68 + 64)
__global__ void __launch_bounds__(256, 2) attn_kernel(const float* __restrict__ dummy) {
    extern __shared__ __align__(16) float sm[];
    float* Qs = sm;                  // [d][t]  64 x 132
    float* Ks = Qs + 64 * 132;       // [d][s]  64 x 68
    float* Vs = Ks + 64 * 68;        // [s][d]  64 x 68
    float* Ps = Vs + 64 * 68;        // [t][s] 128 x 68
    float* bsm = Ps + 128 * 68;      // [64]

    const int tid = threadIdx.x;
    const int tx = tid & 15, ty = tid >> 4;
    const int b = blockIdx.z, h = blockIdx.y, t0 = blockIdx.x * 128;
    const size_t bh = (size_t)(b * Hh + h);
    const float* qbase = g_q + (bh * Tt + t0) * Dd;
    const float* kbase = g_k + bh * Tt * Dd;
    const float* vbase = g_v + bh * Tt * Dd;

    // load Q tile (contiguous 128x64), transpose to [d][t]
#pragma unroll
    for (int r = 0; r < 8; r++) {
        int f = tid + r * 256;       // 2048 float4
        int t = f >> 4, d4 = f & 15;
        float4 v = ((const float4*)qbase)[f];
        Qs[(d4 * 4 + 0) * 132 + t] = v.x;
        Qs[(d4 * 4 + 1) * 132 + t] = v.y;
        Qs[(d4 * 4 + 2) * 132 + t] = v.z;
        Qs[(d4 * 4 + 3) * 132 + t] = v.w;
    }

    float m[8], l[8], O[8][4];
#pragma unroll
    for (int i = 0; i < 8; i++) {
        m[i] = -1e30f; l[i] = 0.f;
#pragma unroll
        for (int j = 0; j < 4; j++) O[i][j] = 0.f;
    }

    for (int s0 = 0; s0 < Tt; s0 += 64) {
        __syncthreads();             // protect Ks/Vs/Ps from previous iter
#pragma unroll
        for (int r = 0; r < 4; r++) {
            int f = tid + r * 256;   // 1024 float4
            int s = f >> 4, d4 = f & 15;
            float4 kv = ((const float4*)(kbase + (size_t)s0 * Dd))[f];
            Ks[(d4 * 4 + 0) * 68 + s] = kv.x;
            Ks[(d4 * 4 + 1) * 68 + s] = kv.y;
            Ks[(d4 * 4 + 2) * 68 + s] = kv.z;
            Ks[(d4 * 4 + 3) * 68 + s] = kv.w;
            float4 vv = ((const float4*)(vbase + (size_t)s0 * Dd))[f];
            *(float4*)&Vs[s * 68 + d4 * 4] = vv;
        }
        if (tid < 64) bsm[tid] = g_bias[b * Tt + s0 + tid];
        __syncthreads();

        // S = Q K^T (+ key bias)
        float S[8][4];
#pragma unroll
        for (int i = 0; i < 8; i++)
#pragma unroll
            for (int j = 0; j < 4; j++) S[i][j] = 0.f;
#pragma unroll
        for (int d = 0; d < 64; d++) {
            float4 a0 = *(const float4*)&Qs[d * 132 + ty * 8];
            float4 a1 = *(const float4*)&Qs[d * 132 + ty * 8 + 4];
            float4 bk = *(const float4*)&Ks[d * 68 + tx * 4];
            float av[8] = {a0.x, a0.y, a0.z, a0.w, a1.x, a1.y, a1.z, a1.w};
            float bv[4] = {bk.x, bk.y, bk.z, bk.w};
#pragma unroll
            for (int i = 0; i < 8; i++)
#pragma unroll
                for (int j = 0; j < 4; j++) S[i][j] += av[i] * bv[j];
        }
        float bj[4] = {bsm[tx * 4], bsm[tx * 4 + 1], bsm[tx * 4 + 2], bsm[tx * 4 + 3]};

        // online softmax (row stats reduced over the 16 tx lanes)
#pragma unroll
        for (int i = 0; i < 8; i++) {
            float rm = -1e30f;
#pragma unroll
            for (int j = 0; j < 4; j++) {
                S[i][j] += bj[j];
                rm = fmaxf(rm, S[i][j]);
            }
            rm = fmaxf(rm, __shfl_xor_sync(0xffffffffu, rm, 1));
            rm = fmaxf(rm, __shfl_xor_sync(0xffffffffu, rm, 2));
            rm = fmaxf(rm, __shfl_xor_sync(0xffffffffu, rm, 4));
            rm = fmaxf(rm, __shfl_xor_sync(0xffffffffu, rm, 8));
            float mnew = fmaxf(m[i], rm);
            float alpha = exp2f((m[i] - mnew) * LOG2E);
            float rs = 0.f;
#pragma unroll
            for (int j = 0; j < 4; j++) {
                S[i][j] = exp2f((S[i][j] - mnew) * LOG2E);  // S now holds P
                rs += S[i][j];
            }
            rs += __shfl_xor_sync(0xffffffffu, rs, 1);
            rs += __shfl_xor_sync(0xffffffffu, rs, 2);
            rs += __shfl_xor_sync(0xffffffffu, rs, 4);
            rs += __shfl_xor_sync(0xffffffffu, rs, 8);
            l[i] = l[i] * alpha + rs;
            m[i] = mnew;
#pragma unroll
            for (int j = 0; j < 4; j++) O[i][j] *= alpha;
            *(float4*)&Ps[(ty * 8 + i) * 68 + tx * 4] =
                make_float4(S[i][0], S[i][1], S[i][2], S[i][3]);
        }
        __syncthreads();

        // O += P V
#pragma unroll 16
        for (int s = 0; s < 64; s++) {
            float4 vv = *(const float4*)&Vs[s * 68 + tx * 4];
#pragma unroll
            for (int i = 0; i < 8; i++) {
                float p = Ps[(ty * 8 + i) * 68 + s];
                O[i][0] += p * vv.x;
                O[i][1] += p * vv.y;
                O[i][2] += p * vv.z;
                O[i][3] += p * vv.w;
            }
        }
    }

    // finalize and write (B,T,C)
#pragma unroll
    for (int i = 0; i < 8; i++) {
        float inv = 1.0f / l[i];
        float4 o = make_float4(O[i][0] * inv, O[i][1] * inv,
                               O[i][2] * inv, O[i][3] * inv);
        *(float4*)(g_ao + ((size_t)(b * Tt + t0 + ty * 8 + i)) * Cc + h * Dd + tx * 4) = o;
    }
    (void)dummy;
}

// ---------------- kernel: output projection ----------------
// g_h[m,j] = g_ao[m,:] . w_out[j,:] + b_out[j];  M = B*T = 8192.
__global__ void __launch_bounds__(256) outproj_kernel(const float* __restrict__ wout,
                                                      const float* __restrict__ bout) {
    __shared__ __align__(16) float As[16 * 132];  // [k][m]
    __shared__ __align__(16) float Bs[16 * 68];   // [k][j]
    const int tid = threadIdx.x;
    const int tx = tid & 15, ty = tid >> 4;
    const int m0 = blockIdx.x * 128;
    const int j0 = blockIdx.y * 64;

    float acc[8][4];
#pragma unroll
    for (int i = 0; i < 8; i++)
#pragma unroll
        for (int j = 0; j < 4; j++) acc[i][j] = 0.f;

    for (int k0 = 0; k0 < Cc; k0 += 16) {
#pragma unroll
        for (int r = 0; r < 2; r++) {
            int f = tid + r * 256;          // 512 float4
            int mm = f >> 2, k4 = f & 3;
            float4 a = *(const float4*)(g_ao + (size_t)(m0 + mm) * Cc + k0 + k4 * 4);
            As[(k4 * 4 + 0) * 132 + mm] = a.x;
            As[(k4 * 4 + 1) * 132 + mm] = a.y;
            As[(k4 * 4 + 2) * 132 + mm] = a.z;
            As[(k4 * 4 + 3) * 132 + mm] = a.w;
        }
        {
            int j = tid >> 2, c4 = tid & 3;
            float4 w = *(const float4*)(wout + (size_t)(j0 + j) * Cc + k0 + c4 * 4);
            Bs[(c4 * 4 + 0) * 68 + j] = w.x;
            Bs[(c4 * 4 + 1) * 68 + j] = w.y;
            Bs[(c4 * 4 + 2) * 68 + j] = w.z;
            Bs[(c4 * 4 + 3) * 68 + j] = w.w;
        }
        __syncthreads();
#pragma unroll
        for (int cc = 0; cc < 16; cc++) {
            float4 a0 = *(const float4*)&As[cc * 132 + ty * 8];
            float4 a1 = *(const float4*)&As[cc * 132 + ty * 8 + 4];
            float4 bb = *(const float4*)&Bs[cc * 68 + tx * 4];
            float av[8] = {a0.x, a0.y, a0.z, a0.w, a1.x, a1.y, a1.z, a1.w};
            float bv[4] = {bb.x, bb.y, bb.z, bb.w};
#pragma unroll
            for (int i = 0; i < 8; i++)
#pragma unroll
                for (int j = 0; j < 4; j++) acc[i][j] += av[i] * bv[j];
        }
        __syncthreads();
    }

    float4 bo = *(const float4*)(bout + j0 + tx * 4);
#pragma unroll
    for (int i = 0; i < 8; i++) {
        float4 o = make_float4(acc[i][0] + bo.x, acc[i][1] + bo.y,
                               acc[i][2] + bo.z, acc[i][3] + bo.w);
        *(float4*)(g_h + (size_t)(m0 + ty * 8 + i) * Cc + j0 + tx * 4) = o;
    }
}

// ---------------- kernel: residual + layernorm + transpose ----------------
// Grid: (T/16, B); 16 t-rows x 512 c per block.
__global__ void __launch_bounds__(256) ln_kernel(const float* __restrict__ x,
                                                 const float* __restrict__ gamma,
                                                 const float* __restrict__ beta,
                                                 float* __restrict__ out) {
    __shared__ __align__(16) float hs[16 * 516];
    __shared__ float smu[16], srs[16];
    const int tid = threadIdx.x;
    const int b = blockIdx.y;
    const int t0 = blockIdx.x * 16;

    // load h tile (coalesced rows)
#pragma unroll
    for (int r = 0; r < 8; r++) {
        int f = tid + r * 256;              // 2048 float4
        int t = f >> 7, c4 = f & 127;
        float4 v = *(const float4*)(g_h + ((size_t)(b * Tt + t0 + t)) * Cc + c4 * 4);
        *(float4*)&hs[t * 516 + c4 * 4] = v;
    }
    __syncthreads();

    // residual add: x is (B,C,T) -> coalesced over t
    const int tt = tid & 15, cg = tid >> 4;
#pragma unroll 8
    for (int k = 0; k < 32; k++) {
        int c = cg * 32 + k;
        hs[tt * 516 + c] += x[(size_t)b * Cc * Tt + (size_t)c * Tt + t0 + tt];
    }
    __syncthreads();

    // stats: 16 lanes per row
    const int row = tid >> 4, l16 = tid & 15;
    float s = 0.f, s2 = 0.f;
#pragma unroll 8
    for (int k = 0; k < 32; k++) {
        float v = hs[row * 516 + l16 + k * 16];
        s += v; s2 += v * v;
    }
    s  += __shfl_xor_sync(0xffffffffu, s, 1);
    s  += __shfl_xor_sync(0xffffffffu, s, 2);
    s  += __shfl_xor_sync(0xffffffffu, s, 4);
    s  += __shfl_xor_sync(0xffffffffu, s, 8);
    s2 += __shfl_xor_sync(0xffffffffu, s2, 1);
    s2 += __shfl_xor_sync(0xffffffffu, s2, 2);
    s2 += __shfl_xor_sync(0xffffffffu, s2, 4);
    s2 += __shfl_xor_sync(0xffffffffu, s2, 8);
    if (l16 == 0) {
        float mu = s * (1.0f / Cc);
        float var = s2 * (1.0f / Cc) - mu * mu;
        smu[row] = mu;
        srs[row] = rsqrtf(var + 1e-5f);
    }
    __syncthreads();

    // normalize + write transposed (B,C,T)
    float mu = smu[tt], rs = srs[tt];
#pragma unroll 8
    for (int k = 0; k < 32; k++) {
        int c = cg * 32 + k;
        float v = (hs[tt * 516 + c] - mu) * rs * gamma[c] + beta[c];
        out[(size_t)b * Cc * Tt + (size_t)c * Tt + t0 + tt] = v;
    }
}

// ---------------- launch ----------------
extern "C" void kernel_launch(void* const* d_in, const int* in_sizes, int n_in,
                              void* d_out, int out_size) {
    const float* x     = (const float*)d_in[0];
    const float* sqi   = (const float*)d_in[1];
    const float* wqkv  = (const float*)d_in[2];
    const float* wout  = (const float*)d_in[3];
    const float* bout  = (const float*)d_in[4];
    const float* wconv = (const float*)d_in[5];
    const float* bconv = (const float*)d_in[6];
    const float* gamma = (const float*)d_in[7];
    const float* beta  = (const float*)d_in[8];
    float* out = (float*)d_out;

    const int attn_smem = ATTN_SMEM_FLOATS * 4;   // 103,680 B
    cudaFuncSetAttribute(attn_kernel, cudaFuncAttributeMaxDynamicSharedMemorySize, attn_smem);

    bias_kernel<<<(Bq * Tt + 255) / 256, 256>>>(sqi, wconv, bconv);
    qkv_kernel<<<dim3(Tt / 128, (3 * Cc) / 64, Bq), 256>>>(x, wqkv);
    attn_kernel<<<dim3(Tt / 128, Hh, Bq), 256, attn_smem>>>(nullptr);
    outproj_kernel<<<dim3((Bq * Tt) / 128, Cc / 64), 256>>>(wout, bout);
    ln_kernel<<<dim3(Tt / 16, Bq), 256>>>(x, gamma, beta, out);
}

// round 2
// speedup vs baseline: 2.3448x; 2.3448x over previous
#include <cuda_runtime.h>
#include <cstdint>

#define Bq 4
#define Cc 512
#define Tt 2048
#define Hh 8
#define Dd 64
#define LOG2E 1.4426950408889634f

// ---------------- scratch (device globals; no allocation) ----------------
__device__ float g_q[Bq * Hh * Tt * Dd];     // (b,h,t,d), pre-scaled by 1/sqrt(D)
__device__ float g_k[Bq * Hh * Tt * Dd];
__device__ float g_v[Bq * Hh * Tt * Dd];
__device__ float g_ao[Bq * Tt * Cc];         // attention output (B,T,C)
__device__ float g_h[Bq * Tt * Cc];          // out-proj result (pre-residual/LN)
__device__ float g_bias[Bq * Tt];            // conv1d key bias

// ---------------- tf32 helpers ----------------
__device__ __forceinline__ uint32_t f2t(float x) {
    uint32_t r;
    asm("cvt.rna.tf32.f32 %0, %1;" : "=r"(r) : "f"(x));
    return r;
}

__device__ __forceinline__ void mma_tf32(float* c, const uint32_t* a,
                                         uint32_t b0, uint32_t b1) {
    asm volatile(
        "mma.sync.aligned.m16n8k8.row.col.f32.tf32.tf32.f32 "
        "{%0,%1,%2,%3}, {%4,%5,%6,%7}, {%8,%9}, {%0,%1,%2,%3};\n"
        : "+f"(c[0]), "+f"(c[1]), "+f"(c[2]), "+f"(c[3])
        : "r"(a[0]), "r"(a[1]), "r"(a[2]), "r"(a[3]), "r"(b0), "r"(b1));
}

// ---------------- kernel: conv1d bias ----------------
__global__ void bias_kernel(const float* __restrict__ sqi,
                            const float* __restrict__ wconv,
                            const float* __restrict__ bconv) {
    int idx = blockIdx.x * 256 + threadIdx.x;
    if (idx >= Bq * Tt) return;
    int b = idx >> 11, t = idx & (Tt - 1);
    float lft = (t > 0)      ? sqi[b * Tt + t - 1] : 0.f;
    float mid = sqi[b * Tt + t];
    float rgt = (t < Tt - 1) ? sqi[b * Tt + t + 1] : 0.f;
    g_bias[idx] = wconv[0] * lft + wconv[1] * mid + wconv[2] * rgt + bconv[0];
}

// ---------------- kernel: QKV projection (tf32 mma) ----------------
// C[t][j] = sum_c x[b][c][t] * w_qkv[j][c].  Tile: 128 t x 64 j, kchunk 32.
// 8 warps; warp w owns t-rows [16w, 16w+16).
__global__ void __launch_bounds__(256) qkv_mma(const float* __restrict__ x,
                                               const float* __restrict__ wqkv) {
    __shared__ uint32_t As[32 * 132];   // [k][t] tf32, pad 132 (frag loads conflict-free)
    __shared__ uint32_t Bs[32 * 72];    // [k][j] tf32, pad 72
    const int tid = threadIdx.x;
    const int w = tid >> 5, lane = tid & 31;
    const int g = lane >> 2, la3 = lane & 3;
    const int t0 = blockIdx.x * 128;
    const int j0 = blockIdx.y * 64;
    const int b = blockIdx.z;
    const float* xb = x + (size_t)b * Cc * Tt;

    float acc[8][4];
#pragma unroll
    for (int j = 0; j < 8; j++)
#pragma unroll
        for (int i = 0; i < 4; i++) acc[j][i] = 0.f;

    for (int k0 = 0; k0 < Cc; k0 += 32) {
        __syncthreads();
        // As: x rows contiguous in t -> float4 loads, STS.128 into [k][t]
#pragma unroll
        for (int r = 0; r < 4; r++) {
            int f = tid + r * 256;          // 1024 float4
            int cc = f >> 5, t4 = f & 31;
            float4 v = *(const float4*)(xb + (size_t)(k0 + cc) * Tt + t0 + 4 * t4);
            uint4 u = make_uint4(f2t(v.x), f2t(v.y), f2t(v.z), f2t(v.w));
            *(uint4*)&As[cc * 132 + 4 * t4] = u;
        }
        // Bs: w_qkv row-major in c -> transpose into [k][j] (conflict-free per warp)
        {
            int j = tid & 63, c4 = tid >> 6;       // c4 in 0..3
#pragma unroll
            for (int r = 0; r < 2; r++) {
                int coff = r * 16 + c4 * 4;
                float4 wv = *(const float4*)(wqkv + (size_t)(j0 + j) * Cc + k0 + coff);
                Bs[(coff + 0) * 72 + j] = f2t(wv.x);
                Bs[(coff + 1) * 72 + j] = f2t(wv.y);
                Bs[(coff + 2) * 72 + j] = f2t(wv.z);
                Bs[(coff + 3) * 72 + j] = f2t(wv.w);
            }
        }
        __syncthreads();
#pragma unroll
        for (int kk = 0; kk < 4; kk++) {
            uint32_t a[4];
            int ab = (8 * kk + la3) * 132 + 16 * w + g;
            a[0] = As[ab];
            a[1] = As[ab + 8];
            a[2] = As[ab + 4 * 132];
            a[3] = As[ab + 4 * 132 + 8];
#pragma unroll
            for (int j = 0; j < 8; j++) {
                uint32_t b0 = Bs[(8 * kk + la3) * 72 + 8 * j + g];
                uint32_t b1 = Bs[(8 * kk + la3 + 4) * 72 + 8 * j + g];
                mma_tf32(acc[j], a, b0, b1);
            }
        }
    }

    const int mat = j0 >> 9;                 // 0=q, 1=k, 2=v
    const int hh = (j0 & 511) >> 6;
    const float scl = (mat == 0) ? 0.125f : 1.0f;
    float* dst = (mat == 0) ? g_q : (mat == 1) ? g_k : g_v;
    dst += ((size_t)(b * Hh + hh)) * Tt * Dd;
    const int r0 = t0 + 16 * w + g;
#pragma unroll
    for (int j = 0; j < 8; j++) {
        int col = 8 * j + 2 * la3;
        *(float2*)(dst + (size_t)r0 * Dd + col) =
            make_float2(acc[j][0] * scl, acc[j][1] * scl);
        *(float2*)(dst + (size_t)(r0 + 8) * Dd + col) =
            make_float2(acc[j][2] * scl, acc[j][3] * scl);
    }
}

// ---------------- kernel: fused flash attention (tf32 mma) ----------------
// Grid (T/128, H, B), 256 thr / 8 warps. Q tile 128, KV chunk 64.
// Warp w owns query rows [16w,16w+16); full 64-wide key/d extent per warp.
#define ATTN_SMEM_WORDS (128 * 68 + 64 * 68 + 64 * 72 + 128 * 68 + 64)
__global__ void __launch_bounds__(256, 2) attn_mma() {
    extern __shared__ uint32_t sm[];
    uint32_t* Qs = sm;                        // [t][d] 128 x 68 (tf32)
    uint32_t* Ks = Qs + 128 * 68;             // [s][d]  64 x 68
    uint32_t* Vs = Ks + 64 * 68;              // [s][d]  64 x 72
    uint32_t* Ps = Vs + 64 * 72;              // [t][s] 128 x 68
    float* bsm = (float*)(Ps + 128 * 68);     // [64]

    const int tid = threadIdx.x;
    const int w = tid >> 5, lane = tid & 31;
    const int g = lane >> 2, la3 = lane & 3;
    const int b = blockIdx.z, h = blockIdx.y, t0 = blockIdx.x * 128;
    const size_t bh = (size_t)(b * Hh + h);
    const float* qbase = g_q + (bh * Tt + t0) * Dd;
    const float* kbase = g_k + bh * Tt * Dd;
    const float* vbase = g_v + bh * Tt * Dd;

    // load Q tile (128x64) -> tf32 [t][d]
#pragma unroll
    for (int r = 0; r < 8; r++) {
        int f = tid + r * 256;                // 2048 float4
        int t = f >> 4, d4 = f & 15;
        float4 v = ((const float4*)qbase)[f];
        uint4 u = make_uint4(f2t(v.x), f2t(v.y), f2t(v.z), f2t(v.w));
        *(uint4*)&Qs[t * 68 + 4 * d4] = u;
    }

    float m0 = -1e30f, m1 = -1e30f, l0 = 0.f, l1 = 0.f;
    float O[8][4];
#pragma unroll
    for (int j = 0; j < 8; j++)
#pragma unroll
        for (int i = 0; i < 4; i++) O[j][i] = 0.f;

    for (int s0 = 0; s0 < Tt; s0 += 64) {
        __syncthreads();
#pragma unroll
        for (int r = 0; r < 4; r++) {
            int f = tid + r * 256;            // 1024 float4
            int s = f >> 4, d4 = f & 15;
            float4 kv = ((const float4*)(kbase + (size_t)s0 * Dd))[f];
            *(uint4*)&Ks[s * 68 + 4 * d4] =
                make_uint4(f2t(kv.x), f2t(kv.y), f2t(kv.z), f2t(kv.w));
            float4 vv = ((const float4*)(vbase + (size_t)s0 * Dd))[f];
            *(uint4*)&Vs[s * 72 + 4 * d4] =
                make_uint4(f2t(vv.x), f2t(vv.y), f2t(vv.z), f2t(vv.w));
        }
        if (tid < 64) bsm[tid] = g_bias[b * Tt + s0 + tid];
        __syncthreads();

        // S = Q K^T
        float S[8][4];
#pragma unroll
        for (int j = 0; j < 8; j++)
#pragma unroll
            for (int i = 0; i < 4; i++) S[j][i] = 0.f;
#pragma unroll
        for (int ks = 0; ks < 8; ks++) {
            uint32_t a[4];
            int ab = (16 * w + g) * 68 + 8 * ks + la3;
            a[0] = Qs[ab];
            a[1] = Qs[ab + 8 * 68];
            a[2] = Qs[ab + 4];
            a[3] = Qs[ab + 8 * 68 + 4];
#pragma unroll
            for (int j = 0; j < 8; j++) {
                uint32_t b0 = Ks[(8 * j + g) * 68 + 8 * ks + la3];
                uint32_t b1 = Ks[(8 * j + g) * 68 + 8 * ks + la3 + 4];
                mma_tf32(S[j], a, b0, b1);
            }
        }

        // bias + row max (rows r0 = 16w+g, r1 = r0+8; cols 8j+2la3,+1)
        float rm0 = -1e30f, rm1 = -1e30f;
#pragma unroll
        for (int j = 0; j < 8; j++) {
            float2 bb = *(const float2*)&bsm[8 * j + 2 * la3];
            S[j][0] += bb.x; S[j][1] += bb.y;
            S[j][2] += bb.x; S[j][3] += bb.y;
            rm0 = fmaxf(rm0, fmaxf(S[j][0], S[j][1]));
            rm1 = fmaxf(rm1, fmaxf(S[j][2], S[j][3]));
        }
        rm0 = fmaxf(rm0, __shfl_xor_sync(0xffffffffu, rm0, 1));
        rm0 = fmaxf(rm0, __shfl_xor_sync(0xffffffffu, rm0, 2));
        rm1 = fmaxf(rm1, __shfl_xor_sync(0xffffffffu, rm1, 1));
        rm1 = fmaxf(rm1, __shfl_xor_sync(0xffffffffu, rm1, 2));
        float mn0 = fmaxf(m0, rm0), mn1 = fmaxf(m1, rm1);
        float al0 = exp2f((m0 - mn0) * LOG2E);
        float al1 = exp2f((m1 - mn1) * LOG2E);
        float rs0 = 0.f, rs1 = 0.f;
#pragma unroll
        for (int j = 0; j < 8; j++) {
            S[j][0] = exp2f((S[j][0] - mn0) * LOG2E);
            S[j][1] = exp2f((S[j][1] - mn0) * LOG2E);
            S[j][2] = exp2f((S[j][2] - mn1) * LOG2E);
            S[j][3] = exp2f((S[j][3] - mn1) * LOG2E);
            rs0 += S[j][0] + S[j][1];
            rs1 += S[j][2] + S[j][3];
            int col = 8 * j + 2 * la3;
            *(uint2*)&Ps[(16 * w + g) * 68 + col] =
                make_uint2(f2t(S[j][0]), f2t(S[j][1]));
            *(uint2*)&Ps[(16 * w + g + 8) * 68 + col] =
                make_uint2(f2t(S[j][2]), f2t(S[j][3]));
        }
        rs0 += __shfl_xor_sync(0xffffffffu, rs0, 1);
        rs0 += __shfl_xor_sync(0xffffffffu, rs0, 2);
        rs1 += __shfl_xor_sync(0xffffffffu, rs1, 1);
        rs1 += __shfl_xor_sync(0xffffffffu, rs1, 2);
        l0 = l0 * al0 + rs0;
        l1 = l1 * al1 + rs1;
        m0 = mn0; m1 = mn1;
#pragma unroll
        for (int j = 0; j < 8; j++) {
            O[j][0] *= al0; O[j][1] *= al0;
            O[j][2] *= al1; O[j][3] *= al1;
        }
        __syncwarp();

        // O += P V
#pragma unroll
        for (int ks = 0; ks < 8; ks++) {
            uint32_t a[4];
            int pb = (16 * w + g) * 68 + 8 * ks + la3;
            a[0] = Ps[pb];
            a[1] = Ps[pb + 8 * 68];
            a[2] = Ps[pb + 4];
            a[3] = Ps[pb + 8 * 68 + 4];
#pragma unroll
            for (int j = 0; j < 8; j++) {
                uint32_t b0 = Vs[(8 * ks + la3) * 72 + 8 * j + g];
                uint32_t b1 = Vs[(8 * ks + la3 + 4) * 72 + 8 * j + g];
                mma_tf32(O[j], a, b0, b1);
            }
        }
    }

    // finalize + write (B,T,C)
    float inv0 = 1.0f / l0, inv1 = 1.0f / l1;
    float* ao = g_ao + ((size_t)(b * Tt + t0 + 16 * w + g)) * Cc + h * Dd;
#pragma unroll
    for (int j = 0; j < 8; j++) {
        int col = 8 * j + 2 * la3;
        *(float2*)(ao + col) = make_float2(O[j][0] * inv0, O[j][1] * inv0);
        *(float2*)(ao + 8 * Cc + col) = make_float2(O[j][2] * inv1, O[j][3] * inv1);
    }
}

// ---------------- kernel: output projection (tf32 mma) ----------------
// g_h[m][j] = g_ao[m][:].w_out[j][:] + b_out[j].  Tile 128 m x 64 j.
__global__ void __launch_bounds__(256) outproj_mma(const float* __restrict__ wout,
                                                   const float* __restrict__ bout) {
    __shared__ uint32_t As[128 * 36];   // [m][k] tf32, pad 36
    __shared__ uint32_t Bs[32 * 72];    // [k][j]
    const int tid = threadIdx.x;
    const int w = tid >> 5, lane = tid & 31;
    const int g = lane >> 2, la3 = lane & 3;
    const int m0 = blockIdx.x * 128;
    const int j0 = blockIdx.y * 64;

    float acc[8][4];
#pragma unroll
    for (int j = 0; j < 8; j++)
#pragma unroll
        for (int i = 0; i < 4; i++) acc[j][i] = 0.f;

    for (int k0 = 0; k0 < Cc; k0 += 32) {
        __syncthreads();
#pragma unroll
        for (int r = 0; r < 4; r++) {
            int f = tid + r * 256;          // 1024 float4
            int mm = f >> 3, k4 = f & 7;
            float4 a = *(const float4*)(g_ao + (size_t)(m0 + mm) * Cc + k0 + 4 * k4);
            *(uint4*)&As[mm * 36 + 4 * k4] =
                make_uint4(f2t(a.x), f2t(a.y), f2t(a.z), f2t(a.w));
        }
        {
            int j = tid & 63, c4 = tid >> 6;
#pragma unroll
            for (int r = 0; r < 2; r++) {
                int coff = r * 16 + c4 * 4;
                float4 wv = *(const float4*)(wout + (size_t)(j0 + j) * Cc + k0 + coff);
                Bs[(coff + 0) * 72 + j] = f2t(wv.x);
                Bs[(coff + 1) * 72 + j] = f2t(wv.y);
                Bs[(coff + 2) * 72 + j] = f2t(wv.z);
                Bs[(coff + 3) * 72 + j] = f2t(wv.w);
            }
        }
        __syncthreads();
#pragma unroll
        for (int kk = 0; kk < 4; kk++) {
            uint32_t a[4];
            int ab = (16 * w + g) * 36 + 8 * kk + la3;
            a[0] = As[ab];
            a[1] = As[ab + 8 * 36];
            a[2] = As[ab + 4];
            a[3] = As[ab + 8 * 36 + 4];
#pragma unroll
            for (int j = 0; j < 8; j++) {
                uint32_t b0 = Bs[(8 * kk + la3) * 72 + 8 * j + g];
                uint32_t b1 = Bs[(8 * kk + la3 + 4) * 72 + 8 * j + g];
                mma_tf32(acc[j], a, b0, b1);
            }
        }
    }

    const int r0 = m0 + 16 * w + g;
#pragma unroll
    for (int j = 0; j < 8; j++) {
        int col = 8 * j + 2 * la3;
        float2 bo = *(const float2*)(bout + j0 + col);
        *(float2*)(g_h + (size_t)r0 * Cc + j0 + col) =
            make_float2(acc[j][0] + bo.x, acc[j][1] + bo.y);
        *(float2*)(g_h + (size_t)(r0 + 8) * Cc + j0 + col) =
            make_float2(acc[j][2] + bo.x, acc[j][3] + bo.y);
    }
}

// ---------------- kernel: residual + layernorm + transpose ----------------
__global__ void __launch_bounds__(256) ln_kernel(const float* __restrict__ x,
                                                 const float* __restrict__ gamma,
                                                 const float* __restrict__ beta,
                                                 float* __restrict__ out) {
    __shared__ __align__(16) float hs[16 * 516];
    __shared__ float smu[16], srs[16];
    const int tid = threadIdx.x;
    const int b = blockIdx.y;
    const int t0 = blockIdx.x * 16;

#pragma unroll
    for (int r = 0; r < 8; r++) {
        int f = tid + r * 256;
        int t = f >> 7, c4 = f & 127;
        float4 v = *(const float4*)(g_h + ((size_t)(b * Tt + t0 + t)) * Cc + c4 * 4);
        *(float4*)&hs[t * 516 + c4 * 4] = v;
    }
    __syncthreads();

    const int tt = tid & 15, cg = tid >> 4;
#pragma unroll 8
    for (int k = 0; k < 32; k++) {
        int c = cg * 32 + k;
        hs[tt * 516 + c] += x[(size_t)b * Cc * Tt + (size_t)c * Tt + t0 + tt];
    }
    __syncthreads();

    const int row = tid >> 4, l16 = tid & 15;
    float s = 0.f, s2 = 0.f;
#pragma unroll 8
    for (int k = 0; k < 32; k++) {
        float v = hs[row * 516 + l16 + k * 16];
        s += v; s2 += v * v;
    }
    s  += __shfl_xor_sync(0xffffffffu, s, 1);
    s  += __shfl_xor_sync(0xffffffffu, s, 2);
    s  += __shfl_xor_sync(0xffffffffu, s, 4);
    s  += __shfl_xor_sync(0xffffffffu, s, 8);
    s2 += __shfl_xor_sync(0xffffffffu, s2, 1);
    s2 += __shfl_xor_sync(0xffffffffu, s2, 2);
    s2 += __shfl_xor_sync(0xffffffffu, s2, 4);
    s2 += __shfl_xor_sync(0xffffffffu, s2, 8);
    if (l16 == 0) {
        float mu = s * (1.0f / Cc);
        float var = s2 * (1.0f / Cc) - mu * mu;
        smu[row] = mu;
        srs[row] = rsqrtf(var + 1e-5f);
    }
    __syncthreads();

    float mu = smu[tt], rs = srs[tt];
#pragma unroll 8
    for (int k = 0; k < 32; k++) {
        int c = cg * 32 + k;
        float v = (hs[tt * 516 + c] - mu) * rs * gamma[c] + beta[c];
        out[(size_t)b * Cc * Tt + (size_t)c * Tt + t0 + tt] = v;
    }
}

// ---------------- launch ----------------
extern "C" void kernel_launch(void* const* d_in, const int* in_sizes, int n_in,
                              void* d_out, int out_size) {
    const float* x     = (const float*)d_in[0];
    const float* sqi   = (const float*)d_in[1];
    const float* wqkv  = (const float*)d_in[2];
    const float* wout  = (const float*)d_in[3];
    const float* bout  = (const float*)d_in[4];
    const float* wconv = (const float*)d_in[5];
    const float* bconv = (const float*)d_in[6];
    const float* gamma = (const float*)d_in[7];
    const float* beta  = (const float*)d_in[8];
    float* out = (float*)d_out;

    const int attn_smem = ATTN_SMEM_WORDS * 4;   // 105,728 B
    cudaFuncSetAttribute(attn_mma, cudaFuncAttributeMaxDynamicSharedMemorySize, attn_smem);

    bias_kernel<<<(Bq * Tt + 255) / 256, 256>>>(sqi, wconv, bconv);
    qkv_mma<<<dim3(Tt / 128, (3 * Cc) / 64, Bq), 256>>>(x, wqkv);
    attn_mma<<<dim3(Tt / 128, Hh, Bq), 256, attn_smem>>>();
    outproj_mma<<<dim3((Bq * Tt) / 128, Cc / 64), 256>>>(wout, bout);
    ln_kernel<<<dim3(Tt / 16, Bq), 256>>>(x, gamma, beta, out);
}

// round 3
// speedup vs baseline: 4.5526x; 1.9416x over previous
#include <cuda_runtime.h>
#include <cstdint>

#define Bq 4
#define Cc 512
#define Tt 2048
#define Hh 8
#define Dd 64
#define LOG2E 1.4426950408889634f

// ---------------- scratch (device globals; no allocation) ----------------
__device__ uint16_t g_q[Bq * Hh * Tt * Dd];   // bf16 (b,h,t,d), Q pre-scaled
__device__ uint16_t g_k[Bq * Hh * Tt * Dd];   // bf16
__device__ uint16_t g_v[Bq * Hh * Tt * Dd];   // bf16
__device__ uint16_t g_ao[Bq * Tt * Cc];       // bf16 attention output (B,T,C)
__device__ float    g_h[Bq * Tt * Cc];        // fp32 out-proj result
__device__ float    g_bias[Bq * Tt];          // conv1d key bias

// ---------------- helpers ----------------
__device__ __forceinline__ uint32_t f2b2(float e0, float e1) {
    uint32_t r;
    asm("cvt.rn.bf16x2.f32 %0, %1, %2;" : "=r"(r) : "f"(e1), "f"(e0));
    return r;   // lower half = e0, upper = e1 (memory order e0,e1)
}

__device__ __forceinline__ void mma_bf16(float* c, const uint32_t* a,
                                         uint32_t b0, uint32_t b1) {
    asm volatile(
        "mma.sync.aligned.m16n8k16.row.col.f32.bf16.bf16.f32 "
        "{%0,%1,%2,%3}, {%4,%5,%6,%7}, {%8,%9}, {%0,%1,%2,%3};\n"
        : "+f"(c[0]), "+f"(c[1]), "+f"(c[2]), "+f"(c[3])
        : "r"(a[0]), "r"(a[1]), "r"(a[2]), "r"(a[3]), "r"(b0), "r"(b1));
}

__device__ __forceinline__ void ldsm4(uint32_t* r, uint32_t a) {
    asm volatile("ldmatrix.sync.aligned.m8n8.x4.shared.b16 {%0,%1,%2,%3}, [%4];"
        : "=r"(r[0]), "=r"(r[1]), "=r"(r[2]), "=r"(r[3]) : "r"(a));
}
__device__ __forceinline__ void ldsm4t(uint32_t* r, uint32_t a) {
    asm volatile("ldmatrix.sync.aligned.m8n8.x4.trans.shared.b16 {%0,%1,%2,%3}, [%4];"
        : "=r"(r[0]), "=r"(r[1]), "=r"(r[2]), "=r"(r[3]) : "r"(a));
}
__device__ __forceinline__ uint32_t sptr(const void* p) {
    return (uint32_t)__cvta_generic_to_shared(p);
}

// ---------------- kernel: conv1d bias ----------------
__global__ void bias_kernel(const float* __restrict__ sqi,
                            const float* __restrict__ wconv,
                            const float* __restrict__ bconv) {
    int idx = blockIdx.x * 256 + threadIdx.x;
    if (idx >= Bq * Tt) return;
    int b = idx >> 11, t = idx & (Tt - 1);
    float lft = (t > 0)      ? sqi[b * Tt + t - 1] : 0.f;
    float mid = sqi[b * Tt + t];
    float rgt = (t < Tt - 1) ? sqi[b * Tt + t + 1] : 0.f;
    g_bias[idx] = wconv[0] * lft + wconv[1] * mid + wconv[2] * rgt + bconv[0];
}

// ---------------- kernel: QKV projection (bf16 mma + ldmatrix) ----------------
// C[t][j] = sum_c x[b][c][t] * w_qkv[j][c].  Tile 128t x 64j, kchunk 64.
// Warp w owns t rows [16w,16w+16).
__global__ void __launch_bounds__(256) qkv_bf16(const float* __restrict__ x,
                                                const float* __restrict__ wqkv) {
    __shared__ uint16_t As[64 * 136];   // [c][t] bf16, pitch 136 (stagger 16B)
    __shared__ uint16_t Bs[64 * 72];    // [j][c] bf16, pitch 72
    const int tid = threadIdx.x;
    const int w = tid >> 5, lane = tid & 31;
    const int g = lane >> 2, la3 = lane & 3;
    const int r8 = lane & 8;                 // matrix row+8 select
    const int c8 = (lane & 16) >> 1;         // matrix col+8 select
    const int t0 = blockIdx.x * 128;
    const int j0 = blockIdx.y * 64;
    const int b = blockIdx.z;
    const float* xb = x + (size_t)b * Cc * Tt;
    const uint32_t Ab = sptr(As), Bb = sptr(Bs);

    float acc[8][4];
#pragma unroll
    for (int j = 0; j < 8; j++)
#pragma unroll
        for (int i = 0; i < 4; i++) acc[j][i] = 0.f;

    for (int k0 = 0; k0 < Cc; k0 += 64) {
        __syncthreads();
        // As: 64c x 128t from x (fp32, t-contiguous) -> bf16 [c][t]
#pragma unroll
        for (int r = 0; r < 8; r++) {
            int f = tid + r * 256;          // 2048 float4
            int c = f >> 5, t4 = (f & 31) * 4;
            float4 v = *(const float4*)(xb + (size_t)(k0 + c) * Tt + t0 + t4);
            *(uint32_t*)&As[c * 136 + t4]     = f2b2(v.x, v.y);
            *(uint32_t*)&As[c * 136 + t4 + 2] = f2b2(v.z, v.w);
        }
        // Bs: 64j x 64c from w_qkv (row-major j,c) -> bf16 [j][c]
#pragma unroll
        for (int r = 0; r < 4; r++) {
            int f = tid + r * 256;          // 1024 float4
            int j = f >> 4, c4 = (f & 15) * 4;
            float4 wv = *(const float4*)(wqkv + (size_t)(j0 + j) * Cc + k0 + c4);
            *(uint32_t*)&Bs[j * 72 + c4]     = f2b2(wv.x, wv.y);
            *(uint32_t*)&Bs[j * 72 + c4 + 2] = f2b2(wv.z, wv.w);
        }
        __syncthreads();
#pragma unroll
        for (int kk = 0; kk < 4; kk++) {
            uint32_t a[4];
            // A via trans-ldsm from [c][t]: row = 16kk+(lane&7)+c8, col = 16w+r8
            ldsm4t(a, Ab + (uint32_t)(((16 * kk + (lane & 7) + c8) * 136 + 16 * w + r8) * 2));
#pragma unroll
            for (int jp = 0; jp < 4; jp++) {
                uint32_t bb[4];
                // B non-trans from [j][c]: row = 16jp+(lane&7)+c8, col = 16kk+r8
                ldsm4(bb, Bb + (uint32_t)(((16 * jp + (lane & 7) + c8) * 72 + 16 * kk + r8) * 2));
                mma_bf16(acc[2 * jp],     a, bb[0], bb[1]);
                mma_bf16(acc[2 * jp + 1], a, bb[2], bb[3]);
            }
        }
    }

    const int mat = j0 >> 9;                 // 0=q, 1=k, 2=v
    const int hh = (j0 & 511) >> 6;
    const float scl = (mat == 0) ? 0.125f : 1.0f;   // fold 1/sqrt(D) into Q (exact)
    uint16_t* dst = (mat == 0) ? g_q : (mat == 1) ? g_k : g_v;
    dst += ((size_t)(b * Hh + hh)) * Tt * Dd;
    const int r0 = t0 + 16 * w + g;
#pragma unroll
    for (int j = 0; j < 8; j++) {
        int col = 8 * j + 2 * la3;
        *(uint32_t*)(dst + (size_t)r0 * Dd + col) =
            f2b2(acc[j][0] * scl, acc[j][1] * scl);
        *(uint32_t*)(dst + (size_t)(r0 + 8) * Dd + col) =
            f2b2(acc[j][2] * scl, acc[j][3] * scl);
    }
}

// ---------------- kernel: fused flash attention (bf16 mma + ldmatrix) --------
// Grid (T/128, H, B), 256 thr / 8 warps. Q tile 128, KV chunk 64.
// smem (bf16 elems): Qs 128x72 | Ks 64x72 | Vs 64x72 | Ps 128x72 | bias 64 f32
#define ATTN_SMEM_BYTES ((128 * 72 + 64 * 72 + 64 * 72 + 128 * 72) * 2 + 64 * 4)
__global__ void __launch_bounds__(256, 2) attn_bf16() {
    extern __shared__ __align__(16) uint16_t sm[];
    uint16_t* Qs = sm;                       // [t][d]
    uint16_t* Ks = Qs + 128 * 72;            // [s][d]
    uint16_t* Vs = Ks + 64 * 72;             // [s][d]
    uint16_t* Ps = Vs + 64 * 72;             // [t][s]
    float* bsm = (float*)(Ps + 128 * 72);    // [64]

    const int tid = threadIdx.x;
    const int w = tid >> 5, lane = tid & 31;
    const int g = lane >> 2, la3 = lane & 3;
    const int r8 = lane & 8;
    const int c8 = (lane & 16) >> 1;
    const int b = blockIdx.z, h = blockIdx.y, t0 = blockIdx.x * 128;
    const size_t bh = (size_t)(b * Hh + h);
    const uint16_t* qbase = g_q + (bh * Tt + t0) * Dd;
    const uint16_t* kbase = g_k + bh * Tt * Dd;
    const uint16_t* vbase = g_v + bh * Tt * Dd;
    const uint32_t Qb = sptr(Qs), Kb = sptr(Ks), Vb = sptr(Vs), Pb = sptr(Ps);

    // load Q tile 128x64 bf16 -> [t][d]
#pragma unroll
    for (int r = 0; r < 4; r++) {
        int f = tid + r * 256;               // 1024 uint4 (8 bf16 each)
        int t = f >> 3, d8 = (f & 7) * 8;
        *(uint4*)&Qs[t * 72 + d8] = *(const uint4*)(qbase + (size_t)t * Dd + d8);
    }

    float m0 = -1e30f, m1 = -1e30f, l0 = 0.f, l1 = 0.f;
    float O[8][4];
#pragma unroll
    for (int j = 0; j < 8; j++)
#pragma unroll
        for (int i = 0; i < 4; i++) O[j][i] = 0.f;

    // per-thread fragment address bases (byte offsets added per-iteration)
    const uint32_t qrow = 16 * w + (lane & 7) + r8;        // A rows (Qs/Ps)
    const uint32_t nrow = (lane & 7) + c8;                  // B rows (Ks)
    const uint32_t vrow = (lane & 7) + r8;                  // B rows (Vs, trans)

    for (int s0 = 0; s0 < Tt; s0 += 64) {
        __syncthreads();
#pragma unroll
        for (int r = 0; r < 2; r++) {
            int f = tid + r * 256;           // 512 uint4
            int s = f >> 3, d8 = (f & 7) * 8;
            *(uint4*)&Ks[s * 72 + d8] = *(const uint4*)(kbase + (size_t)(s0 + s) * Dd + d8);
            *(uint4*)&Vs[s * 72 + d8] = *(const uint4*)(vbase + (size_t)(s0 + s) * Dd + d8);
        }
        if (tid < 64) bsm[tid] = g_bias[b * Tt + s0 + tid];
        __syncthreads();

        // ---- S = Q K^T ----
        float S[8][4];
#pragma unroll
        for (int j = 0; j < 8; j++)
#pragma unroll
            for (int i = 0; i < 4; i++) S[j][i] = 0.f;
#pragma unroll
        for (int kk = 0; kk < 4; kk++) {
            uint32_t a[4];
            ldsm4(a, Qb + (uint32_t)((qrow * 72 + 16 * kk + c8) * 2));
#pragma unroll
            for (int jp = 0; jp < 4; jp++) {
                uint32_t bb[4];
                ldsm4(bb, Kb + (uint32_t)(((16 * jp + nrow) * 72 + 16 * kk + r8) * 2));
                mma_bf16(S[2 * jp],     a, bb[0], bb[1]);
                mma_bf16(S[2 * jp + 1], a, bb[2], bb[3]);
            }
        }

        // ---- bias + online softmax ----
        float rm0 = -1e30f, rm1 = -1e30f;
#pragma unroll
        for (int j = 0; j < 8; j++) {
            float2 bbv = *(const float2*)&bsm[8 * j + 2 * la3];
            S[j][0] += bbv.x; S[j][1] += bbv.y;
            S[j][2] += bbv.x; S[j][3] += bbv.y;
            rm0 = fmaxf(rm0, fmaxf(S[j][0], S[j][1]));
            rm1 = fmaxf(rm1, fmaxf(S[j][2], S[j][3]));
        }
        rm0 = fmaxf(rm0, __shfl_xor_sync(0xffffffffu, rm0, 1));
        rm0 = fmaxf(rm0, __shfl_xor_sync(0xffffffffu, rm0, 2));
        rm1 = fmaxf(rm1, __shfl_xor_sync(0xffffffffu, rm1, 1));
        rm1 = fmaxf(rm1, __shfl_xor_sync(0xffffffffu, rm1, 2));
        float mn0 = fmaxf(m0, rm0), mn1 = fmaxf(m1, rm1);
        float al0 = exp2f((m0 - mn0) * LOG2E);
        float al1 = exp2f((m1 - mn1) * LOG2E);
        float rs0 = 0.f, rs1 = 0.f;
#pragma unroll
        for (int j = 0; j < 8; j++) {
            S[j][0] = exp2f((S[j][0] - mn0) * LOG2E);
            S[j][1] = exp2f((S[j][1] - mn0) * LOG2E);
            S[j][2] = exp2f((S[j][2] - mn1) * LOG2E);
            S[j][3] = exp2f((S[j][3] - mn1) * LOG2E);
            rs0 += S[j][0] + S[j][1];
            rs1 += S[j][2] + S[j][3];
            int col = 8 * j + 2 * la3;
            *(uint32_t*)&Ps[(16 * w + g) * 72 + col]     = f2b2(S[j][0], S[j][1]);
            *(uint32_t*)&Ps[(16 * w + g + 8) * 72 + col] = f2b2(S[j][2], S[j][3]);
        }
        rs0 += __shfl_xor_sync(0xffffffffu, rs0, 1);
        rs0 += __shfl_xor_sync(0xffffffffu, rs0, 2);
        rs1 += __shfl_xor_sync(0xffffffffu, rs1, 1);
        rs1 += __shfl_xor_sync(0xffffffffu, rs1, 2);
        l0 = l0 * al0 + rs0;
        l1 = l1 * al1 + rs1;
        m0 = mn0; m1 = mn1;
#pragma unroll
        for (int j = 0; j < 8; j++) {
            O[j][0] *= al0; O[j][1] *= al0;
            O[j][2] *= al1; O[j][3] *= al1;
        }
        __syncwarp();

        // ---- O += P V ----
#pragma unroll
        for (int kk = 0; kk < 4; kk++) {
            uint32_t a[4];
            ldsm4(a, Pb + (uint32_t)((qrow * 72 + 16 * kk + c8) * 2));
#pragma unroll
            for (int dp = 0; dp < 4; dp++) {
                uint32_t bb[4];
                ldsm4t(bb, Vb + (uint32_t)(((16 * kk + vrow) * 72 + 16 * dp + c8) * 2));
                mma_bf16(O[2 * dp],     a, bb[0], bb[1]);
                mma_bf16(O[2 * dp + 1], a, bb[2], bb[3]);
            }
        }
    }

    // finalize + write bf16 (B,T,C)
    float inv0 = 1.0f / l0, inv1 = 1.0f / l1;
    uint16_t* ao = g_ao + ((size_t)(b * Tt + t0 + 16 * w + g)) * Cc + h * Dd;
#pragma unroll
    for (int j = 0; j < 8; j++) {
        int col = 8 * j + 2 * la3;
        *(uint32_t*)(ao + col)          = f2b2(O[j][0] * inv0, O[j][1] * inv0);
        *(uint32_t*)(ao + 8 * Cc + col) = f2b2(O[j][2] * inv1, O[j][3] * inv1);
    }
}

// ---------------- kernel: output projection (bf16 mma + ldmatrix) ------------
// g_h[m][j] = g_ao[m][:].w_out[j][:] + b_out[j].  Tile 128m x 64j, kchunk 64.
__global__ void __launch_bounds__(256) outproj_bf16(const float* __restrict__ wout,
                                                    const float* __restrict__ bout) {
    __shared__ uint16_t As[128 * 72];   // [m][c]
    __shared__ uint16_t Bs[64 * 72];    // [j][c]
    const int tid = threadIdx.x;
    const int w = tid >> 5, lane = tid & 31;
    const int g = lane >> 2, la3 = lane & 3;
    const int r8 = lane & 8;
    const int c8 = (lane & 16) >> 1;
    const int m0 = blockIdx.x * 128;
    const int j0 = blockIdx.y * 64;
    const uint32_t Ab = sptr(As), Bb = sptr(Bs);

    float acc[8][4];
#pragma unroll
    for (int j = 0; j < 8; j++)
#pragma unroll
        for (int i = 0; i < 4; i++) acc[j][i] = 0.f;

    for (int k0 = 0; k0 < Cc; k0 += 64) {
        __syncthreads();
        // As: 128m x 64c bf16 direct copy from g_ao
#pragma unroll
        for (int r = 0; r < 4; r++) {
            int f = tid + r * 256;          // 1024 uint4
            int m = f >> 3, d8 = (f & 7) * 8;
            *(uint4*)&As[m * 72 + d8] =
                *(const uint4*)(g_ao + (size_t)(m0 + m) * Cc + k0 + d8);
        }
        // Bs: 64j x 64c from w_out fp32
#pragma unroll
        for (int r = 0; r < 4; r++) {
            int f = tid + r * 256;
            int j = f >> 4, c4 = (f & 15) * 4;
            float4 wv = *(const float4*)(wout + (size_t)(j0 + j) * Cc + k0 + c4);
            *(uint32_t*)&Bs[j * 72 + c4]     = f2b2(wv.x, wv.y);
            *(uint32_t*)&Bs[j * 72 + c4 + 2] = f2b2(wv.z, wv.w);
        }
        __syncthreads();
#pragma unroll
        for (int kk = 0; kk < 4; kk++) {
            uint32_t a[4];
            // A non-trans: row = 16w+(lane&7)+r8, col = 16kk+c8
            ldsm4(a, Ab + (uint32_t)(((16 * w + (lane & 7) + r8) * 72 + 16 * kk + c8) * 2));
#pragma unroll
            for (int jp = 0; jp < 4; jp++) {
                uint32_t bb[4];
                ldsm4(bb, Bb + (uint32_t)(((16 * jp + (lane & 7) + c8) * 72 + 16 * kk + r8) * 2));
                mma_bf16(acc[2 * jp],     a, bb[0], bb[1]);
                mma_bf16(acc[2 * jp + 1], a, bb[2], bb[3]);
            }
        }
    }

    const int r0 = m0 + 16 * w + g;
#pragma unroll
    for (int j = 0; j < 8; j++) {
        int col = 8 * j + 2 * la3;
        float2 bo = *(const float2*)(bout + j0 + col);
        *(float2*)(g_h + (size_t)r0 * Cc + j0 + col) =
            make_float2(acc[j][0] + bo.x, acc[j][1] + bo.y);
        *(float2*)(g_h + (size_t)(r0 + 8) * Cc + j0 + col) =
            make_float2(acc[j][2] + bo.x, acc[j][3] + bo.y);
    }
}

// ---------------- kernel: residual + layernorm + transpose ----------------
__global__ void __launch_bounds__(256) ln_kernel(const float* __restrict__ x,
                                                 const float* __restrict__ gamma,
                                                 const float* __restrict__ beta,
                                                 float* __restrict__ out) {
    __shared__ __align__(16) float hs[16 * 516];
    __shared__ float smu[16], srs[16];
    const int tid = threadIdx.x;
    const int b = blockIdx.y;
    const int t0 = blockIdx.x * 16;

#pragma unroll
    for (int r = 0; r < 8; r++) {
        int f = tid + r * 256;
        int t = f >> 7, c4 = f & 127;
        float4 v = *(const float4*)(g_h + ((size_t)(b * Tt + t0 + t)) * Cc + c4 * 4);
        *(float4*)&hs[t * 516 + c4 * 4] = v;
    }
    __syncthreads();

    const int tt = tid & 15, cg = tid >> 4;
#pragma unroll 8
    for (int k = 0; k < 32; k++) {
        int c = cg * 32 + k;
        hs[tt * 516 + c] += x[(size_t)b * Cc * Tt + (size_t)c * Tt + t0 + tt];
    }
    __syncthreads();

    const int row = tid >> 4, l16 = tid & 15;
    float s = 0.f, s2 = 0.f;
#pragma unroll 8
    for (int k = 0; k < 32; k++) {
        float v = hs[row * 516 + l16 + k * 16];
        s += v; s2 += v * v;
    }
    s  += __shfl_xor_sync(0xffffffffu, s, 1);
    s  += __shfl_xor_sync(0xffffffffu, s, 2);
    s  += __shfl_xor_sync(0xffffffffu, s, 4);
    s  += __shfl_xor_sync(0xffffffffu, s, 8);
    s2 += __shfl_xor_sync(0xffffffffu, s2, 1);
    s2 += __shfl_xor_sync(0xffffffffu, s2, 2);
    s2 += __shfl_xor_sync(0xffffffffu, s2, 4);
    s2 += __shfl_xor_sync(0xffffffffu, s2, 8);
    if (l16 == 0) {
        float mu = s * (1.0f / Cc);
        float var = s2 * (1.0f / Cc) - mu * mu;
        smu[row] = mu;
        srs[row] = rsqrtf(var + 1e-5f);
    }
    __syncthreads();

    float mu = smu[tt], rs = srs[tt];
#pragma unroll 8
    for (int k = 0; k < 32; k++) {
        int c = cg * 32 + k;
        float v = (hs[tt * 516 + c] - mu) * rs * gamma[c] + beta[c];
        out[(size_t)b * Cc * Tt + (size_t)c * Tt + t0 + tt] = v;
    }
}

// ---------------- launch ----------------
extern "C" void kernel_launch(void* const* d_in, const int* in_sizes, int n_in,
                              void* d_out, int out_size) {
    const float* x     = (const float*)d_in[0];
    const float* sqi   = (const float*)d_in[1];
    const float* wqkv  = (const float*)d_in[2];
    const float* wout  = (const float*)d_in[3];
    const float* bout  = (const float*)d_in[4];
    const float* wconv = (const float*)d_in[5];
    const float* bconv = (const float*)d_in[6];
    const float* gamma = (const float*)d_in[7];
    const float* beta  = (const float*)d_in[8];
    float* out = (float*)d_out;

    cudaFuncSetAttribute(attn_bf16, cudaFuncAttributeMaxDynamicSharedMemorySize,
                         ATTN_SMEM_BYTES);

    bias_kernel<<<(Bq * Tt + 255) / 256, 256>>>(sqi, wconv, bconv);
    qkv_bf16<<<dim3(Tt / 128, (3 * Cc) / 64, Bq), 256>>>(x, wqkv);
    attn_bf16<<<dim3(Tt / 128, Hh, Bq), 256, ATTN_SMEM_BYTES>>>();
    outproj_bf16<<<dim3((Bq * Tt) / 128, Cc / 64), 256>>>(wout, bout);
    ln_kernel<<<dim3(Tt / 16, Bq), 256>>>(x, gamma, beta, out);
}

// round 4
// speedup vs baseline: 5.6351x; 1.2378x over previous
#include <cuda_runtime.h>
#include <cstdint>

#define Bq 4
#define Cc 512
#define Tt 2048
#define Hh 8
#define Dd 64
#define LOG2E 1.4426950408889634f

// ---------------- scratch (device globals; no allocation) ----------------
__device__ uint16_t g_xb[Bq * Cc * Tt];       // bf16 copy of x
__device__ uint16_t g_wqkvb[3 * Cc * Cc];     // bf16 copy of w_qkv
__device__ uint16_t g_woutb[Cc * Cc];         // bf16 copy of w_out
__device__ uint16_t g_q[Bq * Hh * Tt * Dd];   // bf16, Q pre-scaled by 1/8
__device__ uint16_t g_k[Bq * Hh * Tt * Dd];   // bf16
__device__ uint16_t g_v[Bq * Hh * Tt * Dd];   // fp16
__device__ uint16_t g_ao[Bq * Tt * Cc];       // bf16 attention out (B,T,C)
__device__ float    g_h[Bq * Tt * Cc];        // fp32 out-proj result
__device__ float    g_bias[Bq * Tt];          // conv1d key bias

// ---------------- helpers ----------------
__device__ __forceinline__ uint32_t f2b2(float e0, float e1) {
    uint32_t r;
    asm("cvt.rn.bf16x2.f32 %0, %1, %2;" : "=r"(r) : "f"(e1), "f"(e0));
    return r;
}
__device__ __forceinline__ uint32_t f2h2(float e0, float e1) {
    uint32_t r;
    asm("cvt.rn.f16x2.f32 %0, %1, %2;" : "=r"(r) : "f"(e1), "f"(e0));
    return r;
}
__device__ __forceinline__ uint32_t h2ex2(uint32_t x) {
    uint32_t r;
    asm("ex2.approx.f16x2 %0, %1;" : "=r"(r) : "r"(x));
    return r;
}
__device__ __forceinline__ float2 h22f2(uint32_t p) {
    float2 f;
    asm("{.reg .f16 l,h;\n mov.b32 {l,h}, %2;\n"
        " cvt.f32.f16 %0, l;\n cvt.f32.f16 %1, h;}\n"
        : "=f"(f.x), "=f"(f.y) : "r"(p));
    return f;
}
__device__ __forceinline__ void mma_bf16(float* c, const uint32_t* a,
                                         uint32_t b0, uint32_t b1) {
    asm volatile(
        "mma.sync.aligned.m16n8k16.row.col.f32.bf16.bf16.f32 "
        "{%0,%1,%2,%3}, {%4,%5,%6,%7}, {%8,%9}, {%0,%1,%2,%3};\n"
        : "+f"(c[0]), "+f"(c[1]), "+f"(c[2]), "+f"(c[3])
        : "r"(a[0]), "r"(a[1]), "r"(a[2]), "r"(a[3]), "r"(b0), "r"(b1));
}
__device__ __forceinline__ void mma_f16(float* c, const uint32_t* a,
                                        uint32_t b0, uint32_t b1) {
    asm volatile(
        "mma.sync.aligned.m16n8k16.row.col.f32.f16.f16.f32 "
        "{%0,%1,%2,%3}, {%4,%5,%6,%7}, {%8,%9}, {%0,%1,%2,%3};\n"
        : "+f"(c[0]), "+f"(c[1]), "+f"(c[2]), "+f"(c[3])
        : "r"(a[0]), "r"(a[1]), "r"(a[2]), "r"(a[3]), "r"(b0), "r"(b1));
}
__device__ __forceinline__ void ldsm4(uint32_t* r, uint32_t a) {
    asm volatile("ldmatrix.sync.aligned.m8n8.x4.shared.b16 {%0,%1,%2,%3}, [%4];"
        : "=r"(r[0]), "=r"(r[1]), "=r"(r[2]), "=r"(r[3]) : "r"(a));
}
__device__ __forceinline__ void ldsm4t(uint32_t* r, uint32_t a) {
    asm volatile("ldmatrix.sync.aligned.m8n8.x4.trans.shared.b16 {%0,%1,%2,%3}, [%4];"
        : "=r"(r[0]), "=r"(r[1]), "=r"(r[2]), "=r"(r[3]) : "r"(a));
}
__device__ __forceinline__ uint32_t sptr(const void* p) {
    return (uint32_t)__cvta_generic_to_shared(p);
}
__device__ __forceinline__ void cpa16(uint32_t dst, const void* src) {
    asm volatile("cp.async.cg.shared.global [%0], [%1], 16;\n" :: "r"(dst), "l"(src));
}
__device__ __forceinline__ void cpcommit() {
    asm volatile("cp.async.commit_group;\n");
}
__device__ __forceinline__ void cpwait0() {
    asm volatile("cp.async.wait_group 0;\n");
}

// ---------------- kernel: one-shot bf16 conversions ----------------
__global__ void prep_bf16(const float* __restrict__ x,
                          const float* __restrict__ wqkv,
                          const float* __restrict__ wout) {
    const int NX = Bq * Cc * Tt / 4;
    const int NQ = 3 * Cc * Cc / 4;
    const int NO = Cc * Cc / 4;
    int i = blockIdx.x * 256 + threadIdx.x;
    const float* src;
    uint16_t* dst;
    int off;
    if (i < NX)              { src = x;    dst = g_xb;    off = i; }
    else if (i < NX + NQ)    { src = wqkv; dst = g_wqkvb; off = i - NX; }
    else if (i < NX + NQ + NO){ src = wout; dst = g_woutb; off = i - NX - NQ; }
    else return;
    float4 v = ((const float4*)src)[off];
    ((uint2*)dst)[off] = make_uint2(f2b2(v.x, v.y), f2b2(v.z, v.w));
}

// ---------------- kernel: conv1d bias ----------------
__global__ void bias_kernel(const float* __restrict__ sqi,
                            const float* __restrict__ wconv,
                            const float* __restrict__ bconv) {
    int idx = blockIdx.x * 256 + threadIdx.x;
    if (idx >= Bq * Tt) return;
    int b = idx >> 11, t = idx & (Tt - 1);
    float lft = (t > 0)      ? sqi[b * Tt + t - 1] : 0.f;
    float mid = sqi[b * Tt + t];
    float rgt = (t < Tt - 1) ? sqi[b * Tt + t + 1] : 0.f;
    g_bias[idx] = wconv[0] * lft + wconv[1] * mid + wconv[2] * rgt + bconv[0];
}

// ---------------- kernel: QKV projection (bf16 mma + cp.async pipeline) ------
// C[t][j] = sum_c xb[b][c][t] * wqkv[j][c].  Tile 128t x 128j, kchunk 64.
// smem: As [c][t] 64x136 x2 | Bs [j][c] 128x72 x2   (71,680 B)
#define QKV_SMEM ((2 * 64 * 136 + 2 * 128 * 72) * 2)
__global__ void __launch_bounds__(256, 2) qkv_mm() {
    extern __shared__ __align__(16) uint16_t qsm[];
    uint16_t* As0 = qsm;
    uint16_t* As1 = As0 + 64 * 136;
    uint16_t* Bs0 = As1 + 64 * 136;
    uint16_t* Bs1 = Bs0 + 128 * 72;
    const uint32_t Ab0 = sptr(As0), Ab1 = sptr(As1);
    const uint32_t Bb0 = sptr(Bs0), Bb1 = sptr(Bs1);

    const int tid = threadIdx.x;
    const int w = tid >> 5, lane = tid & 31;
    const int g = lane >> 2, la3 = lane & 3;
    const int r8 = lane & 8;
    const int c8 = (lane & 16) >> 1;
    const int t0 = blockIdx.x * 128;
    const int j0 = blockIdx.y * 128;
    const int b = blockIdx.z;
    const uint16_t* xb = g_xb + (size_t)b * Cc * Tt;

    float acc[16][4];
#pragma unroll
    for (int j = 0; j < 16; j++)
#pragma unroll
        for (int i = 0; i < 4; i++) acc[j][i] = 0.f;

    // prologue: chunk 0
#pragma unroll
    for (int r = 0; r < 4; r++) {
        int f = tid + r * 256;
        int row = f >> 4, c16 = f & 15;
        cpa16(Ab0 + row * 272 + c16 * 16, xb + (size_t)row * Tt + t0 + c16 * 8);
    }
#pragma unroll
    for (int r = 0; r < 4; r++) {
        int f = tid + r * 256;
        int row = f >> 3, c16 = f & 7;
        cpa16(Bb0 + row * 144 + c16 * 16, g_wqkvb + (size_t)(j0 + row) * Cc + c16 * 8);
    }
    cpcommit();

    for (int i = 0; i < 8; i++) {
        cpwait0();
        __syncthreads();
        if (i < 7) {
            int k1 = (i + 1) * 64;
            uint32_t An = (i & 1) ? Ab0 : Ab1;
            uint32_t Bn = (i & 1) ? Bb0 : Bb1;
#pragma unroll
            for (int r = 0; r < 4; r++) {
                int f = tid + r * 256;
                int row = f >> 4, c16 = f & 15;
                cpa16(An + row * 272 + c16 * 16,
                      xb + (size_t)(k1 + row) * Tt + t0 + c16 * 8);
            }
#pragma unroll
            for (int r = 0; r < 4; r++) {
                int f = tid + r * 256;
                int row = f >> 3, c16 = f & 7;
                cpa16(Bn + row * 144 + c16 * 16,
                      g_wqkvb + (size_t)(j0 + row) * Cc + k1 + c16 * 8);
            }
            cpcommit();
        }
        uint32_t Ab = (i & 1) ? Ab1 : Ab0;
        uint32_t Bb = (i & 1) ? Bb1 : Bb0;
#pragma unroll
        for (int kk = 0; kk < 4; kk++) {
            uint32_t a[4];
            ldsm4t(a, Ab + (uint32_t)((16 * kk + (lane & 7) + c8) * 272 + (16 * w + r8) * 2));
#pragma unroll
            for (int jp = 0; jp < 8; jp++) {
                uint32_t bb[4];
                ldsm4(bb, Bb + (uint32_t)((16 * jp + (lane & 7) + c8) * 144 + (16 * kk + r8) * 2));
                mma_bf16(acc[2 * jp],     a, bb[0], bb[1]);
                mma_bf16(acc[2 * jp + 1], a, bb[2], bb[3]);
            }
        }
    }

    const int mat = j0 >> 9;                 // 0=q, 1=k, 2=v
    const float scl = (mat == 0) ? 0.125f : 1.0f;
    const int r0 = t0 + 16 * w + g;
#pragma unroll
    for (int jj = 0; jj < 16; jj++) {
        int col512 = (j0 & 511) + 8 * jj + 2 * la3;
        int hh = col512 >> 6, d = col512 & 63;
        size_t base = ((size_t)(b * Hh + hh) * Tt + r0) * Dd + d;
        if (mat == 2) {
            *(uint32_t*)(g_v + base)            = f2h2(acc[jj][0], acc[jj][1]);
            *(uint32_t*)(g_v + base + 8 * Dd)   = f2h2(acc[jj][2], acc[jj][3]);
        } else {
            uint16_t* dst = (mat == 0) ? g_q : g_k;
            *(uint32_t*)(dst + base)            = f2b2(acc[jj][0] * scl, acc[jj][1] * scl);
            *(uint32_t*)(dst + base + 8 * Dd)   = f2b2(acc[jj][2] * scl, acc[jj][3] * scl);
        }
    }
}

// ---------------- kernel: fused flash attention (f16 exp + cp.async) ---------
// Grid (T/128, H, B), 256 thr / 8 warps.  Q tile 128, KV chunk 64, 2-stage.
#define ATTN_SMEM ((128 * 72 + 4 * 64 * 72 + 128 * 72) * 2 + 2 * 64 * 4)
__global__ void __launch_bounds__(256, 2) attn_mm() {
    extern __shared__ __align__(16) uint16_t asm_[];
    uint16_t* Qs  = asm_;                    // [t][d] 128x72 bf16
    uint16_t* Ks0 = Qs + 128 * 72;           // [s][d] 64x72 bf16 x2
    uint16_t* Ks1 = Ks0 + 64 * 72;
    uint16_t* Vs0 = Ks1 + 64 * 72;           // [s][d] 64x72 f16 x2
    uint16_t* Vs1 = Vs0 + 64 * 72;
    uint16_t* Ps  = Vs1 + 64 * 72;           // [t][s] 128x72 f16
    float* bs0 = (float*)(Ps + 128 * 72);    // [64] x2
    float* bs1 = bs0 + 64;
    const uint32_t Qb = sptr(Qs), Pb = sptr(Ps);
    const uint32_t Kb0 = sptr(Ks0), Kb1 = sptr(Ks1);
    const uint32_t Vb0 = sptr(Vs0), Vb1 = sptr(Vs1);
    const uint32_t Bb0 = sptr(bs0), Bb1 = sptr(bs1);

    const int tid = threadIdx.x;
    const int w = tid >> 5, lane = tid & 31;
    const int g = lane >> 2, la3 = lane & 3;
    const int r8 = lane & 8;
    const int c8 = (lane & 16) >> 1;
    const int b = blockIdx.z, h = blockIdx.y, t0 = blockIdx.x * 128;
    const size_t bh = (size_t)(b * Hh + h);
    const uint16_t* qbase = g_q + (bh * Tt + t0) * Dd;
    const uint16_t* kbase = g_k + bh * Tt * Dd;
    const uint16_t* vbase = g_v + bh * Tt * Dd;

    // prologue: Q + chunk 0
#pragma unroll
    for (int r = 0; r < 4; r++) {
        int f = tid + r * 256;
        int t = f >> 3, c16 = f & 7;
        cpa16(Qb + t * 144 + c16 * 16, qbase + (size_t)t * Dd + c16 * 8);
    }
#pragma unroll
    for (int r = 0; r < 2; r++) {
        int f = tid + r * 256;
        int s = f >> 3, c16 = f & 7;
        cpa16(Kb0 + s * 144 + c16 * 16, kbase + (size_t)s * Dd + c16 * 8);
        cpa16(Vb0 + s * 144 + c16 * 16, vbase + (size_t)s * Dd + c16 * 8);
    }
    if (tid < 16) cpa16(Bb0 + tid * 16, g_bias + b * Tt + tid * 4);
    cpcommit();

    float m0 = -1e30f, m1 = -1e30f, l0 = 0.f, l1 = 0.f;
    float O[8][4];
#pragma unroll
    for (int j = 0; j < 8; j++)
#pragma unroll
        for (int i = 0; i < 4; i++) O[j][i] = 0.f;

    const uint32_t qrow = 16 * w + (lane & 7) + r8;
    const uint32_t nrow = (lane & 7) + c8;
    const uint32_t vrow = (lane & 7) + r8;

    for (int i = 0; i < 32; i++) {
        cpwait0();
        __syncthreads();
        if (i < 31) {
            int s1 = (i + 1) * 64;
            uint32_t Kn = (i & 1) ? Kb0 : Kb1;
            uint32_t Vn = (i & 1) ? Vb0 : Vb1;
            uint32_t Bn = (i & 1) ? Bb0 : Bb1;
#pragma unroll
            for (int r = 0; r < 2; r++) {
                int f = tid + r * 256;
                int s = f >> 3, c16 = f & 7;
                cpa16(Kn + s * 144 + c16 * 16, kbase + (size_t)(s1 + s) * Dd + c16 * 8);
                cpa16(Vn + s * 144 + c16 * 16, vbase + (size_t)(s1 + s) * Dd + c16 * 8);
            }
            if (tid < 16) cpa16(Bn + tid * 16, g_bias + b * Tt + s1 + tid * 4);
            cpcommit();
        }
        const uint32_t Kb = (i & 1) ? Kb1 : Kb0;
        const uint32_t Vb = (i & 1) ? Vb1 : Vb0;
        const float* bsc = (i & 1) ? bs1 : bs0;

        // ---- S = Q K^T (bf16) ----
        float S[8][4];
#pragma unroll
        for (int j = 0; j < 8; j++)
#pragma unroll
            for (int q = 0; q < 4; q++) S[j][q] = 0.f;
#pragma unroll
        for (int kk = 0; kk < 4; kk++) {
            uint32_t a[4];
            ldsm4(a, Qb + (uint32_t)((qrow * 72 + 16 * kk + c8) * 2));
#pragma unroll
            for (int jp = 0; jp < 4; jp++) {
                uint32_t bb[4];
                ldsm4(bb, Kb + (uint32_t)(((16 * jp + nrow) * 72 + 16 * kk + r8) * 2));
                mma_bf16(S[2 * jp],     a, bb[0], bb[1]);
                mma_bf16(S[2 * jp + 1], a, bb[2], bb[3]);
            }
        }

        // ---- bias + online softmax (f16x2 exp) ----
        float rm0 = -1e30f, rm1 = -1e30f;
#pragma unroll
        for (int j = 0; j < 8; j++) {
            float2 bbv = *(const float2*)&bsc[8 * j + 2 * la3];
            S[j][0] += bbv.x; S[j][1] += bbv.y;
            S[j][2] += bbv.x; S[j][3] += bbv.y;
            rm0 = fmaxf(rm0, fmaxf(S[j][0], S[j][1]));
            rm1 = fmaxf(rm1, fmaxf(S[j][2], S[j][3]));
        }
        rm0 = fmaxf(rm0, __shfl_xor_sync(0xffffffffu, rm0, 1));
        rm0 = fmaxf(rm0, __shfl_xor_sync(0xffffffffu, rm0, 2));
        rm1 = fmaxf(rm1, __shfl_xor_sync(0xffffffffu, rm1, 1));
        rm1 = fmaxf(rm1, __shfl_xor_sync(0xffffffffu, rm1, 2));
        float mn0 = fmaxf(m0, rm0), mn1 = fmaxf(m1, rm1);
        float al0 = exp2f((m0 - mn0) * LOG2E);
        float al1 = exp2f((m1 - mn1) * LOG2E);
        float mnl0 = mn0 * LOG2E, mnl1 = mn1 * LOG2E;
        float rs0 = 0.f, rs1 = 0.f;
#pragma unroll
        for (int j = 0; j < 8; j++) {
            uint32_t p01 = h2ex2(f2h2(S[j][0] * LOG2E - mnl0, S[j][1] * LOG2E - mnl0));
            uint32_t p23 = h2ex2(f2h2(S[j][2] * LOG2E - mnl1, S[j][3] * LOG2E - mnl1));
            int col = 8 * j + 2 * la3;
            *(uint32_t*)&Ps[(16 * w + g) * 72 + col]     = p01;
            *(uint32_t*)&Ps[(16 * w + g + 8) * 72 + col] = p23;
            float2 f01 = h22f2(p01);
            float2 f23 = h22f2(p23);
            rs0 += f01.x + f01.y;
            rs1 += f23.x + f23.y;
        }
        rs0 += __shfl_xor_sync(0xffffffffu, rs0, 1);
        rs0 += __shfl_xor_sync(0xffffffffu, rs0, 2);
        rs1 += __shfl_xor_sync(0xffffffffu, rs1, 1);
        rs1 += __shfl_xor_sync(0xffffffffu, rs1, 2);
        l0 = l0 * al0 + rs0;
        l1 = l1 * al1 + rs1;
        m0 = mn0; m1 = mn1;
#pragma unroll
        for (int j = 0; j < 8; j++) {
            O[j][0] *= al0; O[j][1] *= al0;
            O[j][2] *= al1; O[j][3] *= al1;
        }
        __syncwarp();

        // ---- O += P V (f16) ----
#pragma unroll
        for (int kk = 0; kk < 4; kk++) {
            uint32_t a[4];
            ldsm4(a, Pb + (uint32_t)((qrow * 72 + 16 * kk + c8) * 2));
#pragma unroll
            for (int dp = 0; dp < 4; dp++) {
                uint32_t bb[4];
                ldsm4t(bb, Vb + (uint32_t)(((16 * kk + vrow) * 72 + 16 * dp + c8) * 2));
                mma_f16(O[2 * dp],     a, bb[0], bb[1]);
                mma_f16(O[2 * dp + 1], a, bb[2], bb[3]);
            }
        }
    }

    // finalize + write bf16 (B,T,C)
    float inv0 = 1.0f / l0, inv1 = 1.0f / l1;
    uint16_t* ao = g_ao + ((size_t)(b * Tt + t0 + 16 * w + g)) * Cc + h * Dd;
#pragma unroll
    for (int j = 0; j < 8; j++) {
        int col = 8 * j + 2 * la3;
        *(uint32_t*)(ao + col)          = f2b2(O[j][0] * inv0, O[j][1] * inv0);
        *(uint32_t*)(ao + 8 * Cc + col) = f2b2(O[j][2] * inv1, O[j][3] * inv1);
    }
}

// ---------------- kernel: output projection (bf16 mma + cp.async) ------------
// g_h[m][j] = g_ao[m][:].w_out[j][:] + b_out[j].  Tile 128m x 128j, kchunk 64.
#define OUTP_SMEM (4 * 128 * 72 * 2)
__global__ void __launch_bounds__(256, 2) outproj_mm(const float* __restrict__ bout) {
    extern __shared__ __align__(16) uint16_t osm[];
    uint16_t* As0 = osm;                 // [m][c] 128x72 x2
    uint16_t* As1 = As0 + 128 * 72;
    uint16_t* Bs0 = As1 + 128 * 72;      // [j][c] 128x72 x2
    uint16_t* Bs1 = Bs0 + 128 * 72;
    const uint32_t Ab0 = sptr(As0), Ab1 = sptr(As1);
    const uint32_t Bb0 = sptr(Bs0), Bb1 = sptr(Bs1);

    const int tid = threadIdx.x;
    const int w = tid >> 5, lane = tid & 31;
    const int g = lane >> 2, la3 = lane & 3;
    const int r8 = lane & 8;
    const int c8 = (lane & 16) >> 1;
    const int m0 = blockIdx.x * 128;
    const int j0 = blockIdx.y * 128;

    float acc[16][4];
#pragma unroll
    for (int j = 0; j < 16; j++)
#pragma unroll
        for (int i = 0; i < 4; i++) acc[j][i] = 0.f;

#pragma unroll
    for (int r = 0; r < 4; r++) {
        int f = tid + r * 256;
        int row = f >> 3, c16 = f & 7;
        cpa16(Ab0 + row * 144 + c16 * 16, g_ao + (size_t)(m0 + row) * Cc + c16 * 8);
        cpa16(Bb0 + row * 144 + c16 * 16, g_woutb + (size_t)(j0 + row) * Cc + c16 * 8);
    }
    cpcommit();

    for (int i = 0; i < 8; i++) {
        cpwait0();
        __syncthreads();
        if (i < 7) {
            int k1 = (i + 1) * 64;
            uint32_t An = (i & 1) ? Ab0 : Ab1;
            uint32_t Bn = (i & 1) ? Bb0 : Bb1;
#pragma unroll
            for (int r = 0; r < 4; r++) {
                int f = tid + r * 256;
                int row = f >> 3, c16 = f & 7;
                cpa16(An + row * 144 + c16 * 16,
                      g_ao + (size_t)(m0 + row) * Cc + k1 + c16 * 8);
                cpa16(Bn + row * 144 + c16 * 16,
                      g_woutb + (size_t)(j0 + row) * Cc + k1 + c16 * 8);
            }
            cpcommit();
        }
        uint32_t Ab = (i & 1) ? Ab1 : Ab0;
        uint32_t Bb = (i & 1) ? Bb1 : Bb0;
#pragma unroll
        for (int kk = 0; kk < 4; kk++) {
            uint32_t a[4];
            ldsm4(a, Ab + (uint32_t)(((16 * w + (lane & 7) + r8) * 72 + 16 * kk + c8) * 2));
#pragma unroll
            for (int jp = 0; jp < 8; jp++) {
                uint32_t bb[4];
                ldsm4(bb, Bb + (uint32_t)(((16 * jp + (lane & 7) + c8) * 72 + 16 * kk + r8) * 2));
                mma_bf16(acc[2 * jp],     a, bb[0], bb[1]);
                mma_bf16(acc[2 * jp + 1], a, bb[2], bb[3]);
            }
        }
    }

    const int r0 = m0 + 16 * w + g;
#pragma unroll
    for (int jj = 0; jj < 16; jj++) {
        int col = j0 + 8 * jj + 2 * la3;
        float2 bo = *(const float2*)(bout + col);
        *(float2*)(g_h + (size_t)r0 * Cc + col) =
            make_float2(acc[jj][0] + bo.x, acc[jj][1] + bo.y);
        *(float2*)(g_h + (size_t)(r0 + 8) * Cc + col) =
            make_float2(acc[jj][2] + bo.x, acc[jj][3] + bo.y);
    }
}

// ---------------- kernel: residual + layernorm + transpose ----------------
// 32 t-rows per block; smem transposed [c][t] pitch 33.
#define LN_SMEM (Cc * 33 * 4)
__global__ void __launch_bounds__(256) ln_kernel(const float* __restrict__ x,
                                                 const float* __restrict__ gamma,
                                                 const float* __restrict__ beta,
                                                 float* __restrict__ out) {
    extern __shared__ float hs[];            // [c][33]
    __shared__ float smu[32], srs[32], sg[Cc], sb[Cc];
    const int tid = threadIdx.x;
    const int b = blockIdx.y;
    const int t0 = blockIdx.x * 32;

    sg[tid] = gamma[tid]; sg[tid + 256] = gamma[tid + 256];
    sb[tid] = beta[tid];  sb[tid + 256] = beta[tid + 256];

    // load g_h (32t x 512c) -> transposed smem
#pragma unroll
    for (int r = 0; r < 16; r++) {
        int f = tid + r * 256;
        int t = f >> 7, c4 = (f & 127) * 4;
        float4 v = *(const float4*)(g_h + ((size_t)(b * Tt + t0 + t)) * Cc + c4);
        hs[(c4 + 0) * 33 + t] = v.x;
        hs[(c4 + 1) * 33 + t] = v.y;
        hs[(c4 + 2) * 33 + t] = v.z;
        hs[(c4 + 3) * 33 + t] = v.w;
    }
    __syncthreads();

    // residual add: x (B,C,T), coalesced over t
    const int tt = tid & 31, cg = tid >> 5;
#pragma unroll 8
    for (int k = 0; k < 64; k++) {
        int c = cg * 64 + k;
        hs[c * 33 + tt] += x[(size_t)b * Cc * Tt + (size_t)c * Tt + t0 + tt];
    }
    __syncthreads();

    // stats: 8 lanes per t-row
    const int row = tid >> 3, l8 = tid & 7;
    float s = 0.f, s2 = 0.f;
#pragma unroll 8
    for (int k = 0; k < 64; k++) {
        float v = hs[(l8 + 8 * k) * 33 + row];
        s += v; s2 += v * v;
    }
    s  += __shfl_xor_sync(0xffffffffu, s, 1);
    s  += __shfl_xor_sync(0xffffffffu, s, 2);
    s  += __shfl_xor_sync(0xffffffffu, s, 4);
    s2 += __shfl_xor_sync(0xffffffffu, s2, 1);
    s2 += __shfl_xor_sync(0xffffffffu, s2, 2);
    s2 += __shfl_xor_sync(0xffffffffu, s2, 4);
    if (l8 == 0) {
        float mu = s * (1.0f / Cc);
        float var = s2 * (1.0f / Cc) - mu * mu;
        smu[row] = mu;
        srs[row] = rsqrtf(var + 1e-5f);
    }
    __syncthreads();

    // normalize + write transposed (B,C,T)
    float mu = smu[tt], rs = srs[tt];
#pragma unroll 8
    for (int k = 0; k < 64; k++) {
        int c = cg * 64 + k;
        float v = (hs[c * 33 + tt] - mu) * rs * sg[c] + sb[c];
        out[(size_t)b * Cc * Tt + (size_t)c * Tt + t0 + tt] = v;
    }
}

// ---------------- launch ----------------
extern "C" void kernel_launch(void* const* d_in, const int* in_sizes, int n_in,
                              void* d_out, int out_size) {
    const float* x     = (const float*)d_in[0];
    const float* sqi   = (const float*)d_in[1];
    const float* wqkv  = (const float*)d_in[2];
    const float* wout  = (const float*)d_in[3];
    const float* bout  = (const float*)d_in[4];
    const float* wconv = (const float*)d_in[5];
    const float* bconv = (const float*)d_in[6];
    const float* gamma = (const float*)d_in[7];
    const float* beta  = (const float*)d_in[8];
    float* out = (float*)d_out;

    cudaFuncSetAttribute(qkv_mm, cudaFuncAttributeMaxDynamicSharedMemorySize, QKV_SMEM);
    cudaFuncSetAttribute(attn_mm, cudaFuncAttributeMaxDynamicSharedMemorySize, ATTN_SMEM);
    cudaFuncSetAttribute(outproj_mm, cudaFuncAttributeMaxDynamicSharedMemorySize, OUTP_SMEM);
    cudaFuncSetAttribute(ln_kernel, cudaFuncAttributeMaxDynamicSharedMemorySize, LN_SMEM);

    const int NF4 = (Bq * Cc * Tt + 3 * Cc * Cc + Cc * Cc) / 4;
    prep_bf16<<<(NF4 + 255) / 256, 256>>>(x, wqkv, wout);
    bias_kernel<<<(Bq * Tt + 255) / 256, 256>>>(sqi, wconv, bconv);
    qkv_mm<<<dim3(Tt / 128, (3 * Cc) / 128, Bq), 256, QKV_SMEM>>>();
    attn_mm<<<dim3(Tt / 128, Hh, Bq), 256, ATTN_SMEM>>>();
    outproj_mm<<<dim3((Bq * Tt) / 128, Cc / 128), 256, OUTP_SMEM>>>(bout);
    ln_kernel<<<dim3(Tt / 32, Bq), 256, LN_SMEM>>>(x, gamma, beta, out);
}